// round 1
// baseline (speedup 1.0000x reference)
#include <cuda_runtime.h>

#define WINDOW   128
#define EDIM     64
#define SEQ      4096
#define NWIN     (SEQ / WINDOW)   // 32
#define KT       256              // keys per window block (backward + current)
#define THREADS  256
#define SMEMB    (2 * KT * EDIM * 4)   // K tile + V tile, 131072 bytes

// ---- packed f32x2 helpers (sm_10x) ----
__device__ __forceinline__ unsigned long long pack2(float lo, float hi) {
    unsigned long long r;
    asm("mov.b64 %0, {%1, %2};" : "=l"(r) : "f"(lo), "f"(hi));
    return r;
}
__device__ __forceinline__ float2 unpack2(unsigned long long v) {
    float2 f;
    asm("mov.b64 {%0, %1}, %2;" : "=f"(f.x), "=f"(f.y) : "l"(v));
    return f;
}
__device__ __forceinline__ unsigned long long ffma2(unsigned long long a,
                                                    unsigned long long b,
                                                    unsigned long long c) {
    unsigned long long d;
    asm("fma.rn.f32x2 %0, %1, %2, %3;" : "=l"(d) : "l"(a), "l"(b), "l"(c));
    return d;
}

__global__ __launch_bounds__(THREADS, 1)
void local_attn_kernel(const float* __restrict__ q, const float* __restrict__ k,
                       const float* __restrict__ v, float* __restrict__ out)
{
    extern __shared__ float smem[];
    float* sK = smem;                 // KT*EDIM floats
    float* sV = smem + KT * EDIM;     // KT*EDIM floats

    const int win   = blockIdx.x;
    const int bh    = blockIdx.y;
    const int tid   = threadIdx.x;
    const int qrow  = tid & (WINDOW - 1);
    const int khalf = tid >> 7;       // 0: backward window keys, 1: current window keys

    const long long seq_base = (long long)bh * SEQ;
    const int kbase = win * WINDOW - WINDOW;   // first key row in sequence (may be -128)

    // ---- stage K / V tiles into smem (coalesced float4, guard padded rows) ----
    {
        const long long krow0 = seq_base + kbase;   // signed! (may be negative)
        const float4* kg = reinterpret_cast<const float4*>(k) + krow0 * (EDIM / 4);
        const float4* vg = reinterpret_cast<const float4*>(v) + krow0 * (EDIM / 4);
        float4* sK4 = reinterpret_cast<float4*>(sK);
        float4* sV4 = reinterpret_cast<float4*>(sV);
        const int jmin = (kbase >= 0) ? 0 : WINDOW;   // skip out-of-range rows (win==0)
        #pragma unroll
        for (int it = 0; it < (KT * EDIM / 4) / THREADS; ++it) {
            int idx = it * THREADS + tid;
            int j = idx >> 4;                         // 16 float4 per row
            if (j >= jmin) {
                sK4[idx] = kg[idx];
                sV4[idx] = vg[idx];
            }
        }
    }

    // ---- load + scale q row into packed registers ----
    unsigned long long q2[EDIM / 2];
    {
        const float4* qg = reinterpret_cast<const float4*>(
            q + (seq_base + (long long)win * WINDOW + qrow) * EDIM);
        const float scale = 0.125f;   // 64^-0.5
        #pragma unroll
        for (int i = 0; i < EDIM / 4; ++i) {
            float4 t = qg[i];
            q2[2 * i]     = pack2(t.x * scale, t.y * scale);
            q2[2 * i + 1] = pack2(t.z * scale, t.w * scale);
        }
    }

    __syncthreads();

    // ---- single-pass (no-max) softmax-attention over this thread's 128 keys ----
    unsigned long long o2[EDIM / 2];
    #pragma unroll
    for (int i = 0; i < EDIM / 2; ++i) o2[i] = 0ull;
    float l = 0.0f;

    const bool skip = (khalf == 0) && (kbase < 0);   // window 0 has no backward keys
    if (!skip) {
        const int jstart = khalf * WINDOW;
        for (int jj = 0; jj < WINDOW; ++jj) {
            const int j = jstart + jj;
            const ulonglong2* krow = reinterpret_cast<const ulonglong2*>(sK + j * EDIM);
            unsigned long long a0 = 0, a1 = 0, a2 = 0, a3 = 0;
            #pragma unroll
            for (int i = 0; i < EDIM / 4; ++i) {      // 16 iters, 2 packed pairs each
                ulonglong2 kk = krow[i];
                if (i & 1) {
                    a2 = ffma2(q2[2 * i],     kk.x, a2);
                    a3 = ffma2(q2[2 * i + 1], kk.y, a3);
                } else {
                    a0 = ffma2(q2[2 * i],     kk.x, a0);
                    a1 = ffma2(q2[2 * i + 1], kk.y, a1);
                }
            }
            float2 f0 = unpack2(a0), f1 = unpack2(a1), f2 = unpack2(a2), f3 = unpack2(a3);
            float s = ((f0.x + f0.y) + (f1.x + f1.y)) + ((f2.x + f2.y) + (f3.x + f3.y));
            float p = __expf(s);
            // causal: forward half valid iff jj <= qrow; backward half always valid
            if (khalf == 1 && jj > qrow) p = 0.0f;
            l += p;
            unsigned long long p2 = pack2(p, p);
            const ulonglong2* vrow = reinterpret_cast<const ulonglong2*>(sV + j * EDIM);
            #pragma unroll
            for (int i = 0; i < EDIM / 4; ++i) {
                ulonglong2 vv = vrow[i];
                o2[2 * i]     = ffma2(p2, vv.x, o2[2 * i]);
                o2[2 * i + 1] = ffma2(p2, vv.y, o2[2 * i + 1]);
            }
        }
    }

    __syncthreads();   // everyone done reading sK/sV; smem is reusable

    // ---- merge the two key-half partials, normalize, store ----
    const int XS = 66;            // floats per exchange row: l + 64 o + pad
    float* xb = smem;             // 128*66*4 = 33792 B, fits in old sK region
    if (khalf == 1) {
        float* r = xb + qrow * XS;
        r[0] = l;
        #pragma unroll
        for (int i = 0; i < EDIM / 2; ++i) {
            float2 f = unpack2(o2[i]);
            r[1 + 2 * i] = f.x;
            r[2 + 2 * i] = f.y;
        }
    }
    __syncthreads();
    if (khalf == 0) {
        const float* r = xb + qrow * XS;
        l += r[0];
        const float rinv = 1.0f / l;
        float4* og4 = reinterpret_cast<float4*>(
            out + (seq_base + (long long)win * WINDOW + qrow) * EDIM);
        #pragma unroll
        for (int i = 0; i < EDIM / 4; ++i) {
            float2 fa = unpack2(o2[2 * i]);
            float2 fb = unpack2(o2[2 * i + 1]);
            float4 res;
            res.x = (fa.x + r[1 + 4 * i]) * rinv;
            res.y = (fa.y + r[2 + 4 * i]) * rinv;
            res.z = (fb.x + r[3 + 4 * i]) * rinv;
            res.w = (fb.y + r[4 + 4 * i]) * rinv;
            og4[i] = res;
        }
    }
}

extern "C" void kernel_launch(void* const* d_in, const int* in_sizes, int n_in,
                              void* d_out, int out_size)
{
    const float* q = (const float*)d_in[0];
    const float* k = (const float*)d_in[1];
    const float* v = (const float*)d_in[2];
    float* out = (float*)d_out;

    const int bh_count = in_sizes[0] / (SEQ * EDIM);   // b*h = 32

    cudaFuncSetAttribute(local_attn_kernel,
                         cudaFuncAttributeMaxDynamicSharedMemorySize, SMEMB);

    dim3 grid(NWIN, bh_count);
    local_attn_kernel<<<grid, THREADS, SMEMB>>>(q, k, v, out);
}

// round 3
// speedup vs baseline: 4.2823x; 4.2823x over previous
#include <cuda_runtime.h>
#include <cuda_fp16.h>
#include <cstdint>

#define WINDOW   128
#define EDIM     64
#define SEQQ     4096
#define NWIN     32
#define THREADS  256
#define SCALE    0.125f

// padded smem row strides (in halves): +8 keeps the 8 g-lanes on distinct banks
#define QS 72
#define KS 72
#define VS 264

// smem layout (half units)
#define O_Q  0
#define O_K  (O_Q + 128 * QS)            // 9216
#define O_V  (O_K + 256 * KS)            // 27648
#define SMEM_HALVES (O_V + 64 * VS)      // 44544 halves = 89088 bytes
#define SMEM_BYTES  (SMEM_HALVES * 2)

__device__ __forceinline__ void mma16816(float* c, const uint32_t* a, const uint32_t* b) {
    asm volatile(
        "mma.sync.aligned.m16n8k16.row.col.f32.f16.f16.f32 "
        "{%0,%1,%2,%3}, {%4,%5,%6,%7}, {%8,%9}, {%0,%1,%2,%3};"
        : "+f"(c[0]), "+f"(c[1]), "+f"(c[2]), "+f"(c[3])
        : "r"(a[0]), "r"(a[1]), "r"(a[2]), "r"(a[3]), "r"(b[0]), "r"(b[1]));
}

__device__ __forceinline__ uint32_t pack_h2(float x, float y) {
    __half2 h = __floats2half2_rn(x, y);
    return *reinterpret_cast<uint32_t*>(&h);
}

__global__ __launch_bounds__(THREADS, 2)
void lattn_hmma(const float* __restrict__ q, const float* __restrict__ k,
                const float* __restrict__ v, float* __restrict__ out)
{
    extern __shared__ __half smem[];
    __half* sQ = smem + O_Q;
    __half* sK = smem + O_K;
    __half* sV = smem + O_V;   // Vt[e][key]

    const int tid = threadIdx.x;
    const int w   = tid >> 5;          // warp 0..7 -> q rows [16w, 16w+16)
    const int ln  = tid & 31;
    const int g   = ln >> 2;           // group id 0..7
    const int tig = ln & 3;            // thread-in-group 0..3
    const int win = blockIdx.x;
    const int bh  = blockIdx.y;
    const bool have_back = (win > 0);

    const long long qrow0 = (long long)bh * SEQQ + (long long)win * WINDOW;
    const long long krow0 = qrow0 - WINDOW;   // first staged key row (maybe OOB for win 0)

    // ---- stage Q (scaled) ----
    {
        const float2* qg = (const float2*)(q + qrow0 * EDIM);
        #pragma unroll
        for (int it = 0; it < 16; ++it) {
            int idx = it * THREADS + tid;
            int row = idx >> 5, c2 = idx & 31;
            float2 f = qg[idx];
            *(__half2*)&sQ[row * QS + 2 * c2] = __floats2half2_rn(f.x * SCALE, f.y * SCALE);
        }
    }
    // ---- stage K [256][64] ----
    {
        const float2* kg = (const float2*)(k + krow0 * EDIM);
        #pragma unroll
        for (int it = 0; it < 32; ++it) {
            int idx = it * THREADS + tid;
            int row = idx >> 5, c2 = idx & 31;
            if (have_back || row >= WINDOW) {
                float2 f = kg[idx];
                *(__half2*)&sK[row * KS + 2 * c2] = __floats2half2_rn(f.x, f.y);
            }
        }
    }
    // ---- stage Vt [64 e][256 key] (transpose) ----
    {
        const float2* vg = (const float2*)(v + krow0 * EDIM);
        #pragma unroll
        for (int it = 0; it < 32; ++it) {
            int idx = it * THREADS + tid;
            int key = idx >> 5, c2 = idx & 31;
            if (have_back || key >= WINDOW) {
                float2 f = vg[idx];
                int e = 2 * c2;
                sV[e * VS + key]       = __float2half_rn(f.x);
                sV[(e + 1) * VS + key] = __float2half_rn(f.y);
            }
        }
    }
    __syncthreads();

    const int row0 = 16 * w + g;       // window-local q rows this thread owns
    const int row1 = row0 + 8;

    // ---- resident Q A-fragments (4 e-ksteps) ----
    uint32_t qa[4][4];
    #pragma unroll
    for (int ks = 0; ks < 4; ++ks) {
        int e = 2 * tig + 16 * ks;
        qa[ks][0] = *(uint32_t*)&sQ[row0 * QS + e];
        qa[ks][1] = *(uint32_t*)&sQ[row1 * QS + e];
        qa[ks][2] = *(uint32_t*)&sQ[row0 * QS + e + 8];
        qa[ks][3] = *(uint32_t*)&sQ[row1 * QS + e + 8];
    }

    float o[8][4];
    #pragma unroll
    for (int nt = 0; nt < 8; ++nt)
        #pragma unroll
        for (int i = 0; i < 4; ++i) o[nt][i] = 0.f;
    float l0 = 0.f, l1 = 0.f;

    const int cstart = have_back ? 0 : 2;
    #pragma unroll
    for (int c = 0; c < 4; ++c) {
        if (c < cstart) continue;
        const int jb = 64 * c;

        // ---- S chunk: s[nt] = Q x K^T over 64 keys ----
        float s[8][4];
        #pragma unroll
        for (int nt = 0; nt < 8; ++nt)
            #pragma unroll
            for (int i = 0; i < 4; ++i) s[nt][i] = 0.f;

        #pragma unroll
        for (int ks = 0; ks < 4; ++ks) {
            #pragma unroll
            for (int nt = 0; nt < 8; ++nt) {
                const __half* kr = &sK[(jb + 8 * nt + g) * KS + 2 * tig + 16 * ks];
                uint32_t b[2];
                b[0] = *(const uint32_t*)kr;
                b[1] = *(const uint32_t*)(kr + 8);
                mma16816(s[nt], qa[ks], b);
            }
        }

        // ---- mask + exp + row-sum ----
        const bool domask = (c >= 2);
        const int lim0 = row0 + WINDOW;   // key col valid iff col <= lim
        const int lim1 = row1 + WINDOW;
        #pragma unroll
        for (int nt = 0; nt < 8; ++nt) {
            int col0 = jb + 8 * nt + 2 * tig;
            float p0 = (!domask || col0     <= lim0) ? __expf(s[nt][0]) : 0.f;
            float p1 = (!domask || col0 + 1 <= lim0) ? __expf(s[nt][1]) : 0.f;
            float p2 = (!domask || col0     <= lim1) ? __expf(s[nt][2]) : 0.f;
            float p3 = (!domask || col0 + 1 <= lim1) ? __expf(s[nt][3]) : 0.f;
            l0 += p0 + p1;
            l1 += p2 + p3;
            s[nt][0] = p0; s[nt][1] = p1; s[nt][2] = p2; s[nt][3] = p3;
        }

        // ---- repack P into A-fragments (register-local identity) ----
        uint32_t pa[4][4];
        #pragma unroll
        for (int t = 0; t < 4; ++t) {
            pa[t][0] = pack_h2(s[2 * t][0],     s[2 * t][1]);
            pa[t][1] = pack_h2(s[2 * t][2],     s[2 * t][3]);
            pa[t][2] = pack_h2(s[2 * t + 1][0], s[2 * t + 1][1]);
            pa[t][3] = pack_h2(s[2 * t + 1][2], s[2 * t + 1][3]);
        }

        // ---- PV chunk: O += P x V ----
        #pragma unroll
        for (int t = 0; t < 4; ++t) {
            const int k0 = jb + 16 * t + 2 * tig;
            #pragma unroll
            for (int nt = 0; nt < 8; ++nt) {
                const __half* vr = &sV[(g + 8 * nt) * VS + k0];
                uint32_t b[2];
                b[0] = *(const uint32_t*)vr;
                b[1] = *(const uint32_t*)(vr + 8);
                mma16816(o[nt], pa[t], b);
            }
        }
    }

    // ---- reduce l over the quad, normalize, store ----
    l0 += __shfl_xor_sync(0xFFFFFFFFu, l0, 1);
    l0 += __shfl_xor_sync(0xFFFFFFFFu, l0, 2);
    l1 += __shfl_xor_sync(0xFFFFFFFFu, l1, 1);
    l1 += __shfl_xor_sync(0xFFFFFFFFu, l1, 2);
    const float r0 = 1.f / l0;
    const float r1 = 1.f / l1;

    float* ob = out + qrow0 * EDIM;
    #pragma unroll
    for (int nt = 0; nt < 8; ++nt) {
        int e0 = 8 * nt + 2 * tig;
        float2 v0 = make_float2(o[nt][0] * r0, o[nt][1] * r0);
        float2 v1 = make_float2(o[nt][2] * r1, o[nt][3] * r1);
        *(float2*)&ob[(long long)row0 * EDIM + e0] = v0;
        *(float2*)&ob[(long long)row1 * EDIM + e0] = v1;
    }
}

extern "C" void kernel_launch(void* const* d_in, const int* in_sizes, int n_in,
                              void* d_out, int out_size)
{
    const float* q = (const float*)d_in[0];
    const float* k = (const float*)d_in[1];
    const float* v = (const float*)d_in[2];
    float* out = (float*)d_out;

    const int bh_count = in_sizes[0] / (SEQQ * EDIM);   // b*h = 32

    cudaFuncSetAttribute(lattn_hmma, cudaFuncAttributeMaxDynamicSharedMemorySize, SMEM_BYTES);

    dim3 grid(NWIN, bh_count);
    lattn_hmma<<<grid, THREADS, SMEM_BYTES>>>(q, k, v, out);
}

// round 4
// speedup vs baseline: 5.7264x; 1.3372x over previous
#include <cuda_runtime.h>
#include <cuda_fp16.h>
#include <cstdint>

#define WINDOW   128
#define EDIM     64
#define SEQQ     4096
#define NWIN     32
#define THREADS  256
#define SCALE    0.125f

// padded smem row stride (halves): 72 halves = 144B -> 8 ldmatrix row ptrs hit
// bank groups 0,4,8,...,28 (x4 banks each) -> conflict-free
#define RS 72

// smem layout (half units): Q[128], K[256], V[256] all row-major [row][e]
#define O_Q  0
#define O_K  (O_Q + 128 * RS)
#define O_V  (O_K + 256 * RS)
#define SMEM_HALVES (O_V + 256 * RS)
#define SMEM_BYTES  (SMEM_HALVES * 2)     // 92160

__device__ __forceinline__ void mma16816(float* c, const uint32_t* a, const uint32_t* b) {
    asm volatile(
        "mma.sync.aligned.m16n8k16.row.col.f32.f16.f16.f32 "
        "{%0,%1,%2,%3}, {%4,%5,%6,%7}, {%8,%9}, {%0,%1,%2,%3};"
        : "+f"(c[0]), "+f"(c[1]), "+f"(c[2]), "+f"(c[3])
        : "r"(a[0]), "r"(a[1]), "r"(a[2]), "r"(a[3]), "r"(b[0]), "r"(b[1]));
}

__device__ __forceinline__ void ldm_x4(uint32_t* r, uint32_t addr) {
    asm volatile("ldmatrix.sync.aligned.m8n8.x4.shared.b16 {%0,%1,%2,%3}, [%4];"
        : "=r"(r[0]), "=r"(r[1]), "=r"(r[2]), "=r"(r[3]) : "r"(addr));
}
__device__ __forceinline__ void ldm_x4_t(uint32_t* r, uint32_t addr) {
    asm volatile("ldmatrix.sync.aligned.m8n8.x4.trans.shared.b16 {%0,%1,%2,%3}, [%4];"
        : "=r"(r[0]), "=r"(r[1]), "=r"(r[2]), "=r"(r[3]) : "r"(addr));
}

__device__ __forceinline__ uint32_t smem_u32(const void* p) {
    uint32_t a;
    asm("{ .reg .u64 t; cvta.to.shared.u64 t, %1; cvt.u32.u64 %0, t; }" : "=r"(a) : "l"(p));
    return a;
}

__device__ __forceinline__ uint32_t pack_h2(float x, float y) {
    __half2 h = __floats2half2_rn(x, y);
    return *reinterpret_cast<uint32_t*>(&h);
}

__global__ __launch_bounds__(THREADS, 2)
void lattn_hmma(const float* __restrict__ q, const float* __restrict__ k,
                const float* __restrict__ v, float* __restrict__ out)
{
    extern __shared__ __half smem[];
    const uint32_t sb  = smem_u32(smem);
    const uint32_t sbQ = sb + O_Q * 2;
    const uint32_t sbK = sb + O_K * 2;
    const uint32_t sbV = sb + O_V * 2;

    const int tid = threadIdx.x;
    const int w   = tid >> 5;          // warp 0..7 -> q rows [16w, 16w+16)
    const int ln  = tid & 31;
    const int g   = ln >> 2;
    const int tig = ln & 3;
    const int win = blockIdx.x;
    const int bh  = blockIdx.y;
    const bool have_back = (win > 0);

    const long long qrow0 = (long long)bh * SEQQ + (long long)win * WINDOW;
    const long long krow0 = qrow0 - WINDOW;

    // ---- stage Q (scaled), K, V : identical row-major coalesced half2 ----
    {
        const float2* qg = (const float2*)(q + qrow0 * EDIM);
        #pragma unroll
        for (int it = 0; it < 16; ++it) {
            int idx = it * THREADS + tid;
            int row = idx >> 5, c2 = idx & 31;
            float2 f = qg[idx];
            *(__half2*)&smem[O_Q + row * RS + 2 * c2] =
                __floats2half2_rn(f.x * SCALE, f.y * SCALE);
        }
        const float2* kg = (const float2*)(k + krow0 * EDIM);
        const float2* vg = (const float2*)(v + krow0 * EDIM);
        #pragma unroll
        for (int it = 0; it < 32; ++it) {
            int idx = it * THREADS + tid;
            int row = idx >> 5, c2 = idx & 31;
            if (have_back || row >= WINDOW) {
                float2 fk = kg[idx];
                float2 fv = vg[idx];
                *(__half2*)&smem[O_K + row * RS + 2 * c2] = __floats2half2_rn(fk.x, fk.y);
                *(__half2*)&smem[O_V + row * RS + 2 * c2] = __floats2half2_rn(fv.x, fv.y);
            }
        }
    }
    __syncthreads();

    const int row0 = 16 * w + g;
    const int row1 = row0 + 8;

    // per-lane ldmatrix base offsets (bytes)
    // K (non-trans B): matrices {keys+0..7 e+0}, {keys+0..7 e+8}, {keys+8.. e+0}, {keys+8.. e+8}
    const uint32_t koff = 2u * (((ln & 7) + ((ln & 16) >> 1)) * RS + (ln & 8));
    // V (trans B) / Q (A): matrices {rows+0..7 c+0}, {rows+8.. c+0}, {rows+0..7 c+8}, {rows+8.. c+8}
    const uint32_t voff = 2u * (((ln & 7) + (ln & 8)) * RS + ((ln & 16) >> 1));

    // ---- resident Q A-fragments (4 e-ksteps) via ldmatrix.x4 ----
    uint32_t qa[4][4];
    {
        const uint32_t qbase = sbQ + 2u * (16 * w) * RS + voff;
        #pragma unroll
        for (int ks = 0; ks < 4; ++ks)
            ldm_x4(qa[ks], qbase + 2u * 16 * ks);
    }

    float o[8][4];
    #pragma unroll
    for (int nt = 0; nt < 8; ++nt)
        #pragma unroll
        for (int i = 0; i < 4; ++i) o[nt][i] = 0.f;
    float l0 = 0.f, l1 = 0.f;

    const int cstart = have_back ? 0 : 2;
    #pragma unroll
    for (int c = 0; c < 4; ++c) {
        if (c < cstart) continue;
        const int jb = 64 * c;

        // ---- S chunk: Q x K^T over 64 keys ----
        float s[8][4];
        #pragma unroll
        for (int nt = 0; nt < 8; ++nt)
            #pragma unroll
            for (int i = 0; i < 4; ++i) s[nt][i] = 0.f;

        const uint32_t kcb = sbK + 2u * jb * RS + koff;
        #pragma unroll
        for (int ks = 0; ks < 4; ++ks) {
            #pragma unroll
            for (int ntp = 0; ntp < 4; ++ntp) {
                uint32_t b[4];
                ldm_x4(b, kcb + 2u * (16 * ntp * RS + 16 * ks));
                mma16816(s[2 * ntp],     qa[ks], b);
                mma16816(s[2 * ntp + 1], qa[ks], b + 2);
            }
        }

        // ---- mask + exp + row-sum ----
        const bool domask = (c >= 2);
        const int lim0 = row0 + WINDOW;
        const int lim1 = row1 + WINDOW;
        #pragma unroll
        for (int nt = 0; nt < 8; ++nt) {
            int col0 = jb + 8 * nt + 2 * tig;
            float p0 = (!domask || col0     <= lim0) ? __expf(s[nt][0]) : 0.f;
            float p1 = (!domask || col0 + 1 <= lim0) ? __expf(s[nt][1]) : 0.f;
            float p2 = (!domask || col0     <= lim1) ? __expf(s[nt][2]) : 0.f;
            float p3 = (!domask || col0 + 1 <= lim1) ? __expf(s[nt][3]) : 0.f;
            l0 += p0 + p1;
            l1 += p2 + p3;
            s[nt][0] = p0; s[nt][1] = p1; s[nt][2] = p2; s[nt][3] = p3;
        }

        // ---- repack P into A-fragments (register-local identity) ----
        uint32_t pa[4][4];
        #pragma unroll
        for (int t = 0; t < 4; ++t) {
            pa[t][0] = pack_h2(s[2 * t][0],     s[2 * t][1]);
            pa[t][1] = pack_h2(s[2 * t][2],     s[2 * t][3]);
            pa[t][2] = pack_h2(s[2 * t + 1][0], s[2 * t + 1][1]);
            pa[t][3] = pack_h2(s[2 * t + 1][2], s[2 * t + 1][3]);
        }

        // ---- PV chunk: O += P x V  (V^T fragments via ldmatrix.trans) ----
        const uint32_t vcb = sbV + 2u * jb * RS + voff;
        #pragma unroll
        for (int t = 0; t < 4; ++t) {
            #pragma unroll
            for (int ep = 0; ep < 4; ++ep) {
                uint32_t b[4];
                ldm_x4_t(b, vcb + 2u * (16 * t * RS + 16 * ep));
                mma16816(o[2 * ep],     pa[t], b);
                mma16816(o[2 * ep + 1], pa[t], b + 2);
            }
        }
    }

    // ---- reduce l over the quad, normalize, store ----
    l0 += __shfl_xor_sync(0xFFFFFFFFu, l0, 1);
    l0 += __shfl_xor_sync(0xFFFFFFFFu, l0, 2);
    l1 += __shfl_xor_sync(0xFFFFFFFFu, l1, 1);
    l1 += __shfl_xor_sync(0xFFFFFFFFu, l1, 2);
    const float r0 = 1.f / l0;
    const float r1 = 1.f / l1;

    float* ob = out + qrow0 * EDIM;
    #pragma unroll
    for (int nt = 0; nt < 8; ++nt) {
        int e0 = 8 * nt + 2 * tig;
        float2 v0 = make_float2(o[nt][0] * r0, o[nt][1] * r0);
        float2 v1 = make_float2(o[nt][2] * r1, o[nt][3] * r1);
        *(float2*)&ob[(long long)row0 * EDIM + e0] = v0;
        *(float2*)&ob[(long long)row1 * EDIM + e0] = v1;
    }
}

extern "C" void kernel_launch(void* const* d_in, const int* in_sizes, int n_in,
                              void* d_out, int out_size)
{
    const float* q = (const float*)d_in[0];
    const float* k = (const float*)d_in[1];
    const float* v = (const float*)d_in[2];
    float* out = (float*)d_out;

    const int bh_count = in_sizes[0] / (SEQQ * EDIM);   // b*h = 32

    cudaFuncSetAttribute(lattn_hmma, cudaFuncAttributeMaxDynamicSharedMemorySize, SMEM_BYTES);

    dim3 grid(NWIN, bh_count);
    lattn_hmma<<<grid, THREADS, SMEM_BYTES>>>(q, k, v, out);
}